// round 12
// baseline (speedup 1.0000x reference)
#include <cuda_runtime.h>
#include <cuda_bf16.h>

// Sliding-window attention B=1,S=2048,H=8,D=64,win +-64, fp32 in/out.
// FlashAttention-v2-style warp-MMA kernel with split-bf16 emulated fp32.
// R10: 8 warps/block (2-way key split per 16-query group) for 16 warps/SM.
// Warp (wq, sp): queries q0+16wq..+15; sp=0 -> key-steps 0..4, sp=1 -> 5..8.
// Split partials combined through reused smem tile.

#define S_LEN  2048
#define NH     8
#define HD     64
#define WIN    64
#define TQ     64
#define NROWS  192
#define ROWB   128                  // bytes per bf16 row (64*2)
#define ARR    (NROWS*ROWB)         // 24576 B per array
#define SMEM_BYTES (4*ARR)          // Khi,Klo,Vhi,Vlo = 98304 B

__device__ __forceinline__ unsigned pk(float lo, float hi) {
    unsigned d;
    asm("cvt.rn.bf16x2.f32 %0, %1, %2;" : "=r"(d) : "f"(hi), "f"(lo));
    return d;
}
__device__ __forceinline__ float up_lo(unsigned v) { return __uint_as_float(v << 16); }
__device__ __forceinline__ float up_hi(unsigned v) { return __uint_as_float(v & 0xffff0000u); }
__device__ __forceinline__ float ex2(float x) {
    float y; asm("ex2.approx.f32 %0, %1;" : "=f"(y) : "f"(x)); return y;
}
__device__ __forceinline__ unsigned s2u(const void* p) {
    unsigned a;
    asm("{ .reg .u64 t; cvta.to.shared.u64 t, %1; cvt.u32.u64 %0, t; }"
        : "=r"(a) : "l"(p));
    return a;
}
__device__ __forceinline__ void ldsm4(unsigned& r0, unsigned& r1, unsigned& r2,
                                      unsigned& r3, unsigned a) {
    asm volatile("ldmatrix.sync.aligned.m8n8.x4.shared.b16 {%0,%1,%2,%3}, [%4];"
                 : "=r"(r0), "=r"(r1), "=r"(r2), "=r"(r3) : "r"(a));
}
__device__ __forceinline__ void ldsm4t(unsigned& r0, unsigned& r1, unsigned& r2,
                                       unsigned& r3, unsigned a) {
    asm volatile("ldmatrix.sync.aligned.m8n8.x4.trans.shared.b16 {%0,%1,%2,%3}, [%4];"
                 : "=r"(r0), "=r"(r1), "=r"(r2), "=r"(r3) : "r"(a));
}
__device__ __forceinline__ void mma16816(float c[4], const unsigned a[4],
                                         unsigned b0, unsigned b1) {
    asm volatile(
        "mma.sync.aligned.m16n8k16.row.col.f32.bf16.bf16.f32 "
        "{%0,%1,%2,%3}, {%4,%5,%6,%7}, {%8,%9}, {%0,%1,%2,%3};"
        : "+f"(c[0]), "+f"(c[1]), "+f"(c[2]), "+f"(c[3])
        : "r"(a[0]), "r"(a[1]), "r"(a[2]), "r"(a[3]), "r"(b0), "r"(b1));
}

__global__ void __launch_bounds__(256, 2) swa_mma(
    const float* __restrict__ Q,
    const float* __restrict__ K,
    const float* __restrict__ V,
    float* __restrict__ O)
{
    extern __shared__ char smem[];
    const unsigned sb = s2u(smem);

    const int h    = blockIdx.y;
    const int q0   = blockIdx.x * TQ;
    const int tid  = threadIdx.x;
    const int lane = tid & 31;
    const int w    = tid >> 5;
    const int wq   = w & 3;             // query group of 16
    const int sp   = w >> 2;            // key split 0/1
    const int base = q0 - WIN;          // global key of smem row 0

    // ---- stage K,V as split-bf16 into swizzled smem ----
    for (int idx = tid; idx < NROWS * 16; idx += 256) {
        const int row = idx >> 4;
        const int c   = idx & 15;
        const int k   = base + row;
        float4 kf = make_float4(0.f,0.f,0.f,0.f);
        float4 vf = make_float4(0.f,0.f,0.f,0.f);
        if ((unsigned)k < S_LEN) {
            const int off = (k * NH + h) * 16 + c;
            kf = reinterpret_cast<const float4*>(K)[off];
            vf = reinterpret_cast<const float4*>(V)[off];
        }
        const unsigned so = row * ROWB + ((((c >> 1) ^ (row & 7)) << 4)) + ((c & 1) << 3);
        unsigned kh0 = pk(kf.x, kf.y), kh1 = pk(kf.z, kf.w);
        unsigned kl0 = pk(kf.x - up_lo(kh0), kf.y - up_hi(kh0));
        unsigned kl1 = pk(kf.z - up_lo(kh1), kf.w - up_hi(kh1));
        unsigned vh0 = pk(vf.x, vf.y), vh1 = pk(vf.z, vf.w);
        unsigned vl0 = pk(vf.x - up_lo(vh0), vf.y - up_hi(vh0));
        unsigned vl1 = pk(vf.z - up_lo(vh1), vf.w - up_hi(vh1));
        *reinterpret_cast<uint2*>(smem + so)            = make_uint2(kh0, kh1);
        *reinterpret_cast<uint2*>(smem + ARR + so)      = make_uint2(kl0, kl1);
        *reinterpret_cast<uint2*>(smem + 2*ARR + so)    = make_uint2(vh0, vh1);
        *reinterpret_cast<uint2*>(smem + 3*ARR + so)    = make_uint2(vl0, vl1);
    }

    // ---- per-thread Q fragments (m16k16), scaled by 0.125*log2(e), split ----
    const int qw   = q0 + 16 * wq;
    const int r    = lane >> 2;
    const int col0 = (lane & 3) * 2;
    const float sc = 0.125f * 1.44269504088896340736f;

    unsigned qh[4][4], ql[4][4];
    {
        const float* Q0 = Q + (size_t)((qw + r)     * NH + h) * HD;
        const float* Q8 = Q + (size_t)((qw + r + 8) * NH + h) * HD;
        #pragma unroll
        for (int kt = 0; kt < 4; kt++) {
            float2 e0 = *reinterpret_cast<const float2*>(Q0 + kt*16 + col0);
            float2 e1 = *reinterpret_cast<const float2*>(Q8 + kt*16 + col0);
            float2 e2 = *reinterpret_cast<const float2*>(Q0 + kt*16 + col0 + 8);
            float2 e3 = *reinterpret_cast<const float2*>(Q8 + kt*16 + col0 + 8);
            e0.x*=sc; e0.y*=sc; e1.x*=sc; e1.y*=sc;
            e2.x*=sc; e2.y*=sc; e3.x*=sc; e3.y*=sc;
            qh[kt][0]=pk(e0.x,e0.y); qh[kt][1]=pk(e1.x,e1.y);
            qh[kt][2]=pk(e2.x,e2.y); qh[kt][3]=pk(e3.x,e3.y);
            ql[kt][0]=pk(e0.x-up_lo(qh[kt][0]), e0.y-up_hi(qh[kt][0]));
            ql[kt][1]=pk(e1.x-up_lo(qh[kt][1]), e1.y-up_hi(qh[kt][1]));
            ql[kt][2]=pk(e2.x-up_lo(qh[kt][2]), e2.y-up_hi(qh[kt][2]));
            ql[kt][3]=pk(e3.x-up_lo(qh[kt][3]), e3.y-up_hi(qh[kt][3]));
        }
    }

    __syncthreads();

    // ---- main loop: this split's key-steps of 16 keys ----
    float o[8][4];
    #pragma unroll
    for (int n = 0; n < 8; n++)
        #pragma unroll
        for (int j = 0; j < 4; j++) o[n][j] = 0.f;
    float lr = 0.f, lr8 = 0.f;

    const int gq   = lane >> 3;        // ldmatrix address group
    const int iq   = lane & 7;
    const int wrow = 16 * wq;
    const int rA0  = wrow + ((gq >> 1) << 3) + iq;   // QK addr row (pre ks)
    const int rB0  = wrow + ((gq & 1) << 3) + iq;    // PV addr row (pre ks)
    const int kbw  = base + wrow;                    // global key of warp row 0

    const int ksb = sp ? 5 : 0;
    const int kse = sp ? 9 : 5;

    #pragma unroll 1
    for (int ks = ksb; ks < kse; ks++) {
        // ---- QK: two n-tiles (keys ks*16..+7, +8..+15) ----
        float c0[4] = {0,0,0,0}, c1[4] = {0,0,0,0};
        const int rowA = rA0 + ks * 16;
        const unsigned aAbase = sb + rowA * ROWB;
        #pragma unroll
        for (int kt = 0; kt < 4; kt++) {
            const unsigned aK = aAbase + ((((2*kt) + (gq & 1)) ^ (rowA & 7)) << 4);
            unsigned b0,b1,b2,b3, l0,l1,l2,l3;
            ldsm4(b0,b1,b2,b3, aK);          // K hi
            ldsm4(l0,l1,l2,l3, aK + ARR);    // K lo
            mma16816(c0, qh[kt], b0, b1);  mma16816(c1, qh[kt], b2, b3);
            mma16816(c0, qh[kt], l0, l1);  mma16816(c1, qh[kt], l2, l3);
            mma16816(c0, ql[kt], b0, b1);  mma16816(c1, ql[kt], b2, b3);
        }

        // ---- mask + exp2 (scores already in log2 domain) ----
        const int nta  = 2 * ks;
        const int d00  = nta*8 + col0 - 64 - r;   // key - query for c=0,h=0
        const int keyb = kbw + nta*8 + col0;
        #pragma unroll
        for (int t2 = 0; t2 < 2; t2++) {
            float* cc = t2 ? c1 : c0;
            const int dd = d00 + 8*t2;
            const int kk = keyb + 8*t2;
            float p0 = ((unsigned)(dd + 64)     <= 128 && (unsigned)kk     < S_LEN) ? ex2(cc[0]) : 0.f;
            float p1 = ((unsigned)(dd + 65)     <= 128 && (unsigned)(kk+1) < S_LEN) ? ex2(cc[1]) : 0.f;
            float p2 = ((unsigned)(dd + 56)     <= 128 && (unsigned)kk     < S_LEN) ? ex2(cc[2]) : 0.f;
            float p3 = ((unsigned)(dd + 57)     <= 128 && (unsigned)(kk+1) < S_LEN) ? ex2(cc[3]) : 0.f;
            cc[0]=p0; cc[1]=p1; cc[2]=p2; cc[3]=p3;
            lr  += p0 + p1;
            lr8 += p2 + p3;
        }

        // ---- P fragments (accum layout == A layout), split-bf16 ----
        unsigned ph[4], pl[4];
        ph[0] = pk(c0[0], c0[1]); ph[1] = pk(c0[2], c0[3]);
        ph[2] = pk(c1[0], c1[1]); ph[3] = pk(c1[2], c1[3]);
        pl[0] = pk(c0[0]-up_lo(ph[0]), c0[1]-up_hi(ph[0]));
        pl[1] = pk(c0[2]-up_lo(ph[1]), c0[3]-up_hi(ph[1]));
        pl[2] = pk(c1[0]-up_lo(ph[2]), c1[1]-up_hi(ph[2]));
        pl[3] = pk(c1[2]-up_lo(ph[3]), c1[3]-up_hi(ph[3]));

        // ---- PV: 8 n-tiles of dims ----
        const int rowB = rB0 + ks * 16;
        const unsigned aBbase = sb + 2*ARR + rowB * ROWB;
        #pragma unroll
        for (int dq = 0; dq < 4; dq++) {
            const unsigned aV = aBbase + ((((2*dq) + (gq >> 1)) ^ (rowB & 7)) << 4);
            unsigned v0,v1,v2,v3, u0,u1,u2,u3;
            ldsm4t(v0,v1,v2,v3, aV);         // V hi
            ldsm4t(u0,u1,u2,u3, aV + ARR);   // V lo
            mma16816(o[2*dq],   ph, v0, v1);  mma16816(o[2*dq+1], ph, v2, v3);
            mma16816(o[2*dq],   ph, u0, u1);  mma16816(o[2*dq+1], ph, u2, u3);
            mma16816(o[2*dq],   pl, v0, v1);  mma16816(o[2*dq+1], pl, v2, v3);
        }
    }

    // ---- combine the two key splits through reused smem tile ----
    __syncthreads();                 // all tile reads done; smem is scratch now

    float* scr  = reinterpret_cast<float*>(smem);      // [4][32][36] floats
    float* scrL = scr + 4*32*36;                        // [4][32][2]

    if (sp == 1) {
        float4* ap = reinterpret_cast<float4*>(scr + (wq*32 + lane) * 36);
        #pragma unroll
        for (int n = 0; n < 8; n++)
            ap[n] = make_float4(o[n][0], o[n][1], o[n][2], o[n][3]);
        scrL[(wq*32 + lane)*2 + 0] = lr;
        scrL[(wq*32 + lane)*2 + 1] = lr8;
    }
    __syncthreads();

    if (sp == 0) {
        const float4* ap = reinterpret_cast<const float4*>(scr + (wq*32 + lane) * 36);
        #pragma unroll
        for (int n = 0; n < 8; n++) {
            const float4 b = ap[n];
            o[n][0] += b.x; o[n][1] += b.y; o[n][2] += b.z; o[n][3] += b.w;
        }
        lr  += scrL[(wq*32 + lane)*2 + 0];
        lr8 += scrL[(wq*32 + lane)*2 + 1];

        lr  += __shfl_xor_sync(0xffffffffu, lr, 1);
        lr  += __shfl_xor_sync(0xffffffffu, lr, 2);
        lr8 += __shfl_xor_sync(0xffffffffu, lr8, 1);
        lr8 += __shfl_xor_sync(0xffffffffu, lr8, 2);
        const float inv  = 1.0f / lr;
        const float inv8 = 1.0f / lr8;

        float* O0 = O + (size_t)((qw + r)     * NH + h) * HD;
        float* O8 = O + (size_t)((qw + r + 8) * NH + h) * HD;
        #pragma unroll
        for (int n = 0; n < 8; n++) {
            *reinterpret_cast<float2*>(O0 + n*8 + col0) =
                make_float2(o[n][0] * inv,  o[n][1] * inv);
            *reinterpret_cast<float2*>(O8 + n*8 + col0) =
                make_float2(o[n][2] * inv8, o[n][3] * inv8);
        }
    }
}

extern "C" void kernel_launch(void* const* d_in, const int* in_sizes, int n_in,
                              void* d_out, int out_size)
{
    const float* Q = (const float*)d_in[0];
    const float* K = (const float*)d_in[1];
    const float* V = (const float*)d_in[2];
    float* O = (float*)d_out;

    cudaFuncSetAttribute(swa_mma, cudaFuncAttributeMaxDynamicSharedMemorySize,
                         SMEM_BYTES);

    dim3 grid(S_LEN / TQ, NH);
    swa_mma<<<grid, 256, SMEM_BYTES>>>(Q, K, V, O);
}

// round 14
// speedup vs baseline: 1.0021x; 1.0021x over previous
#include <cuda_runtime.h>
#include <cuda_bf16.h>

// Sliding-window attention B=1,S=2048,H=8,D=64,win +-64, fp32 in/out.
// FlashAttention-v2-style warp-MMA kernel with split-bf16 emulated fp32.
// R13 (rerun; prior attempt hit a container-infra failure, no data):
// QK accumulators split into 4 independent HMMA chains (c0,c1,d0,d1),
// Q gmem loads hoisted above staging, staging loop unrolled for MLP.
// 8 warps/block: warp (wq,sp) handles queries q0+16wq..+15, key-steps
// sp=0 -> 0..4, sp=1 -> 5..8; partials combined through reused smem.

#define S_LEN  2048
#define NH     8
#define HD     64
#define WIN    64
#define TQ     64
#define NROWS  192
#define ROWB   128                  // bytes per bf16 row (64*2)
#define ARR    (NROWS*ROWB)         // 24576 B per array
#define SMEM_BYTES (4*ARR)          // Khi,Klo,Vhi,Vlo = 98304 B

__device__ __forceinline__ unsigned pk(float lo, float hi) {
    unsigned d;
    asm("cvt.rn.bf16x2.f32 %0, %1, %2;" : "=r"(d) : "f"(hi), "f"(lo));
    return d;
}
__device__ __forceinline__ float up_lo(unsigned v) { return __uint_as_float(v << 16); }
__device__ __forceinline__ float up_hi(unsigned v) { return __uint_as_float(v & 0xffff0000u); }
__device__ __forceinline__ float ex2(float x) {
    float y; asm("ex2.approx.f32 %0, %1;" : "=f"(y) : "f"(x)); return y;
}
__device__ __forceinline__ unsigned s2u(const void* p) {
    unsigned a;
    asm("{ .reg .u64 t; cvta.to.shared.u64 t, %1; cvt.u32.u64 %0, t; }"
        : "=r"(a) : "l"(p));
    return a;
}
__device__ __forceinline__ void ldsm4(unsigned& r0, unsigned& r1, unsigned& r2,
                                      unsigned& r3, unsigned a) {
    asm volatile("ldmatrix.sync.aligned.m8n8.x4.shared.b16 {%0,%1,%2,%3}, [%4];"
                 : "=r"(r0), "=r"(r1), "=r"(r2), "=r"(r3) : "r"(a));
}
__device__ __forceinline__ void ldsm4t(unsigned& r0, unsigned& r1, unsigned& r2,
                                       unsigned& r3, unsigned a) {
    asm volatile("ldmatrix.sync.aligned.m8n8.x4.trans.shared.b16 {%0,%1,%2,%3}, [%4];"
                 : "=r"(r0), "=r"(r1), "=r"(r2), "=r"(r3) : "r"(a));
}
__device__ __forceinline__ void mma16816(float c[4], const unsigned a[4],
                                         unsigned b0, unsigned b1) {
    asm volatile(
        "mma.sync.aligned.m16n8k16.row.col.f32.bf16.bf16.f32 "
        "{%0,%1,%2,%3}, {%4,%5,%6,%7}, {%8,%9}, {%0,%1,%2,%3};"
        : "+f"(c[0]), "+f"(c[1]), "+f"(c[2]), "+f"(c[3])
        : "r"(a[0]), "r"(a[1]), "r"(a[2]), "r"(a[3]), "r"(b0), "r"(b1));
}

__global__ void __launch_bounds__(256, 2) swa_mma(
    const float* __restrict__ Q,
    const float* __restrict__ K,
    const float* __restrict__ V,
    float* __restrict__ O)
{
    extern __shared__ char smem[];
    const unsigned sb = s2u(smem);

    const int h    = blockIdx.y;
    const int q0   = blockIdx.x * TQ;
    const int tid  = threadIdx.x;
    const int lane = tid & 31;
    const int w    = tid >> 5;
    const int wq   = w & 3;             // query group of 16
    const int sp   = w >> 2;            // key split 0/1
    const int base = q0 - WIN;          // global key of smem row 0

    // ---- hoist Q gmem loads (overlap DRAM latency with staging below) ----
    const int qw   = q0 + 16 * wq;
    const int r    = lane >> 2;
    const int col0 = (lane & 3) * 2;
    float2 e[4][4];
    {
        const float* Q0 = Q + (size_t)((qw + r)     * NH + h) * HD;
        const float* Q8 = Q + (size_t)((qw + r + 8) * NH + h) * HD;
        #pragma unroll
        for (int kt = 0; kt < 4; kt++) {
            e[kt][0] = *reinterpret_cast<const float2*>(Q0 + kt*16 + col0);
            e[kt][1] = *reinterpret_cast<const float2*>(Q8 + kt*16 + col0);
            e[kt][2] = *reinterpret_cast<const float2*>(Q0 + kt*16 + col0 + 8);
            e[kt][3] = *reinterpret_cast<const float2*>(Q8 + kt*16 + col0 + 8);
        }
    }

    // ---- stage K,V as split-bf16 into swizzled smem ----
    #pragma unroll 2
    for (int idx = tid; idx < NROWS * 16; idx += 256) {
        const int row = idx >> 4;
        const int c   = idx & 15;
        const int k   = base + row;
        float4 kf = make_float4(0.f,0.f,0.f,0.f);
        float4 vf = make_float4(0.f,0.f,0.f,0.f);
        if ((unsigned)k < S_LEN) {
            const int off = (k * NH + h) * 16 + c;
            kf = reinterpret_cast<const float4*>(K)[off];
            vf = reinterpret_cast<const float4*>(V)[off];
        }
        const unsigned so = row * ROWB + ((((c >> 1) ^ (row & 7)) << 4)) + ((c & 1) << 3);
        unsigned kh0 = pk(kf.x, kf.y), kh1 = pk(kf.z, kf.w);
        unsigned kl0 = pk(kf.x - up_lo(kh0), kf.y - up_hi(kh0));
        unsigned kl1 = pk(kf.z - up_lo(kh1), kf.w - up_hi(kh1));
        unsigned vh0 = pk(vf.x, vf.y), vh1 = pk(vf.z, vf.w);
        unsigned vl0 = pk(vf.x - up_lo(vh0), vf.y - up_hi(vh0));
        unsigned vl1 = pk(vf.z - up_lo(vh1), vf.w - up_hi(vh1));
        *reinterpret_cast<uint2*>(smem + so)            = make_uint2(kh0, kh1);
        *reinterpret_cast<uint2*>(smem + ARR + so)      = make_uint2(kl0, kl1);
        *reinterpret_cast<uint2*>(smem + 2*ARR + so)    = make_uint2(vh0, vh1);
        *reinterpret_cast<uint2*>(smem + 3*ARR + so)    = make_uint2(vl0, vl1);
    }

    // ---- build Q fragments (scaled by 0.125*log2(e)), split-bf16 ----
    const float sc = 0.125f * 1.44269504088896340736f;
    unsigned qh[4][4], ql[4][4];
    #pragma unroll
    for (int kt = 0; kt < 4; kt++) {
        #pragma unroll
        for (int j = 0; j < 4; j++) {
            float x = e[kt][j].x * sc, y = e[kt][j].y * sc;
            qh[kt][j] = pk(x, y);
            ql[kt][j] = pk(x - up_lo(qh[kt][j]), y - up_hi(qh[kt][j]));
        }
    }

    __syncthreads();

    // ---- main loop: this split's key-steps of 16 keys ----
    float o[8][4];
    #pragma unroll
    for (int n = 0; n < 8; n++)
        #pragma unroll
        for (int j = 0; j < 4; j++) o[n][j] = 0.f;
    float lr = 0.f, lr8 = 0.f;

    const int gq   = lane >> 3;        // ldmatrix address group
    const int iq   = lane & 7;
    const int wrow = 16 * wq;
    const int rA0  = wrow + ((gq >> 1) << 3) + iq;   // QK addr row (pre ks)
    const int rB0  = wrow + ((gq & 1) << 3) + iq;    // PV addr row (pre ks)
    const int kbw  = base + wrow;                    // global key of warp row 0

    const int ksb = sp ? 5 : 0;
    const int kse = sp ? 9 : 5;

    #pragma unroll 1
    for (int ks = ksb; ks < kse; ks++) {
        // ---- QK: two n-tiles, FOUR independent accumulator chains ----
        float c0[4] = {0,0,0,0}, c1[4] = {0,0,0,0};
        float d0[4] = {0,0,0,0}, d1[4] = {0,0,0,0};
        const int rowA = rA0 + ks * 16;
        const unsigned aAbase = sb + rowA * ROWB;
        #pragma unroll
        for (int kt = 0; kt < 4; kt++) {
            const unsigned aK = aAbase + ((((2*kt) + (gq & 1)) ^ (rowA & 7)) << 4);
            unsigned b0,b1,b2,b3, l0,l1,l2,l3;
            ldsm4(b0,b1,b2,b3, aK);          // K hi
            ldsm4(l0,l1,l2,l3, aK + ARR);    // K lo
            mma16816(c0, qh[kt], b0, b1);    // chain c0: qh*Khi
            mma16816(c1, qh[kt], b2, b3);    // chain c1: qh*Khi
            mma16816(d0, qh[kt], l0, l1);    // chain d0: qh*Klo + ql*Khi
            mma16816(d1, qh[kt], l2, l3);    // chain d1
            mma16816(d0, ql[kt], b0, b1);
            mma16816(d1, ql[kt], b2, b3);
        }
        #pragma unroll
        for (int j = 0; j < 4; j++) { c0[j] += d0[j]; c1[j] += d1[j]; }

        // ---- mask + exp2 (scores already in log2 domain) ----
        const int nta  = 2 * ks;
        const int d00  = nta*8 + col0 - 64 - r;   // key - query for c=0,h=0
        const int keyb = kbw + nta*8 + col0;
        #pragma unroll
        for (int t2 = 0; t2 < 2; t2++) {
            float* cc = t2 ? c1 : c0;
            const int dd = d00 + 8*t2;
            const int kk = keyb + 8*t2;
            float p0 = ((unsigned)(dd + 64)     <= 128 && (unsigned)kk     < S_LEN) ? ex2(cc[0]) : 0.f;
            float p1 = ((unsigned)(dd + 65)     <= 128 && (unsigned)(kk+1) < S_LEN) ? ex2(cc[1]) : 0.f;
            float p2 = ((unsigned)(dd + 56)     <= 128 && (unsigned)kk     < S_LEN) ? ex2(cc[2]) : 0.f;
            float p3 = ((unsigned)(dd + 57)     <= 128 && (unsigned)(kk+1) < S_LEN) ? ex2(cc[3]) : 0.f;
            cc[0]=p0; cc[1]=p1; cc[2]=p2; cc[3]=p3;
            lr  += p0 + p1;
            lr8 += p2 + p3;
        }

        // ---- P fragments (accum layout == A layout), split-bf16 ----
        unsigned ph[4], pl[4];
        ph[0] = pk(c0[0], c0[1]); ph[1] = pk(c0[2], c0[3]);
        ph[2] = pk(c1[0], c1[1]); ph[3] = pk(c1[2], c1[3]);
        pl[0] = pk(c0[0]-up_lo(ph[0]), c0[1]-up_hi(ph[0]));
        pl[1] = pk(c0[2]-up_lo(ph[1]), c0[3]-up_hi(ph[1]));
        pl[2] = pk(c1[0]-up_lo(ph[2]), c1[1]-up_hi(ph[2]));
        pl[3] = pk(c1[2]-up_lo(ph[3]), c1[3]-up_hi(ph[3]));

        // ---- PV: 8 n-tiles of dims (8 independent o-chains) ----
        const int rowB = rB0 + ks * 16;
        const unsigned aBbase = sb + 2*ARR + rowB * ROWB;
        #pragma unroll
        for (int dq = 0; dq < 4; dq++) {
            const unsigned aV = aBbase + ((((2*dq) + (gq >> 1)) ^ (rowB & 7)) << 4);
            unsigned v0,v1,v2,v3, u0,u1,u2,u3;
            ldsm4t(v0,v1,v2,v3, aV);         // V hi
            ldsm4t(u0,u1,u2,u3, aV + ARR);   // V lo
            mma16816(o[2*dq],   ph, v0, v1);  mma16816(o[2*dq+1], ph, v2, v3);
            mma16816(o[2*dq],   ph, u0, u1);  mma16816(o[2*dq+1], ph, u2, u3);
            mma16816(o[2*dq],   pl, v0, v1);  mma16816(o[2*dq+1], pl, v2, v3);
        }
    }

    // ---- combine the two key splits through reused smem tile ----
    __syncthreads();                 // all tile reads done; smem is scratch now

    float* scr  = reinterpret_cast<float*>(smem);      // [4][32][36] floats
    float* scrL = scr + 4*32*36;                        // [4][32][2]

    if (sp == 1) {
        float4* ap = reinterpret_cast<float4*>(scr + (wq*32 + lane) * 36);
        #pragma unroll
        for (int n = 0; n < 8; n++)
            ap[n] = make_float4(o[n][0], o[n][1], o[n][2], o[n][3]);
        scrL[(wq*32 + lane)*2 + 0] = lr;
        scrL[(wq*32 + lane)*2 + 1] = lr8;
    }
    __syncthreads();

    if (sp == 0) {
        const float4* ap = reinterpret_cast<const float4*>(scr + (wq*32 + lane) * 36);
        #pragma unroll
        for (int n = 0; n < 8; n++) {
            const float4 b = ap[n];
            o[n][0] += b.x; o[n][1] += b.y; o[n][2] += b.z; o[n][3] += b.w;
        }
        lr  += scrL[(wq*32 + lane)*2 + 0];
        lr8 += scrL[(wq*32 + lane)*2 + 1];

        lr  += __shfl_xor_sync(0xffffffffu, lr, 1);
        lr  += __shfl_xor_sync(0xffffffffu, lr, 2);
        lr8 += __shfl_xor_sync(0xffffffffu, lr8, 1);
        lr8 += __shfl_xor_sync(0xffffffffu, lr8, 2);
        const float inv  = 1.0f / lr;
        const float inv8 = 1.0f / lr8;

        float* O0 = O + (size_t)((qw + r)     * NH + h) * HD;
        float* O8 = O + (size_t)((qw + r + 8) * NH + h) * HD;
        #pragma unroll
        for (int n = 0; n < 8; n++) {
            *reinterpret_cast<float2*>(O0 + n*8 + col0) =
                make_float2(o[n][0] * inv,  o[n][1] * inv);
            *reinterpret_cast<float2*>(O8 + n*8 + col0) =
                make_float2(o[n][2] * inv8, o[n][3] * inv8);
        }
    }
}

extern "C" void kernel_launch(void* const* d_in, const int* in_sizes, int n_in,
                              void* d_out, int out_size)
{
    const float* Q = (const float*)d_in[0];
    const float* K = (const float*)d_in[1];
    const float* V = (const float*)d_in[2];
    float* O = (float*)d_out;

    cudaFuncSetAttribute(swa_mma, cudaFuncAttributeMaxDynamicSharedMemorySize,
                         SMEM_BYTES);

    dim3 grid(S_LEN / TQ, NH);
    swa_mma<<<grid, 256, SMEM_BYTES>>>(Q, K, V, O);
}

// round 15
// speedup vs baseline: 1.0064x; 1.0043x over previous
#include <cuda_runtime.h>
#include <cuda_fp16.h>

// Sliding-window attention B=1,S=2048,H=8,D=64,win +-64, fp32 in/out.
// R15: fp16 tensor-core path spending the 1e-3 error budget:
//   QK: q split fp16 hi+lo (22-bit), K single fp16 -> 2-term MMA (err ~3e-4)
//   PV: P single fp16, V single fp16 -> 1-term MMA (err ~4e-4)
// vs R14 split-bf16: MMAs 48->24/key-step, LDSM 16->8, staging halved,
// smem 98->49 KB. Layouts/swizzle/masking identical to the verified R9 path.
// 8 warps/block: warp (wq,sp): queries q0+16wq..+15, key-steps sp=0:0..4,
// sp=1:5..8; partials combined through reused smem.

#define S_LEN  2048
#define NH     8
#define HD     64
#define WIN    64
#define TQ     64
#define NROWS  192
#define ROWB   128                  // bytes per fp16 row (64*2)
#define ARR    (NROWS*ROWB)         // 24576 B per array
#define SMEM_BYTES (2*ARR)          // Kh, Vh = 49152 B

__device__ __forceinline__ unsigned pk16(float lo, float hi) {
    unsigned d;
    asm("cvt.rn.f16x2.f32 %0, %1, %2;" : "=r"(d) : "f"(hi), "f"(lo));
    return d;
}
__device__ __forceinline__ float2 up16(unsigned v) {
    __half2 h = *reinterpret_cast<__half2*>(&v);
    return __half22float2(h);
}
__device__ __forceinline__ float ex2(float x) {
    float y; asm("ex2.approx.f32 %0, %1;" : "=f"(y) : "f"(x)); return y;
}
__device__ __forceinline__ unsigned s2u(const void* p) {
    unsigned a;
    asm("{ .reg .u64 t; cvta.to.shared.u64 t, %1; cvt.u32.u64 %0, t; }"
        : "=r"(a) : "l"(p));
    return a;
}
__device__ __forceinline__ void ldsm4(unsigned& r0, unsigned& r1, unsigned& r2,
                                      unsigned& r3, unsigned a) {
    asm volatile("ldmatrix.sync.aligned.m8n8.x4.shared.b16 {%0,%1,%2,%3}, [%4];"
                 : "=r"(r0), "=r"(r1), "=r"(r2), "=r"(r3) : "r"(a));
}
__device__ __forceinline__ void ldsm4t(unsigned& r0, unsigned& r1, unsigned& r2,
                                       unsigned& r3, unsigned a) {
    asm volatile("ldmatrix.sync.aligned.m8n8.x4.trans.shared.b16 {%0,%1,%2,%3}, [%4];"
                 : "=r"(r0), "=r"(r1), "=r"(r2), "=r"(r3) : "r"(a));
}
__device__ __forceinline__ void mma16816(float c[4], const unsigned a[4],
                                         unsigned b0, unsigned b1) {
    asm volatile(
        "mma.sync.aligned.m16n8k16.row.col.f32.f16.f16.f32 "
        "{%0,%1,%2,%3}, {%4,%5,%6,%7}, {%8,%9}, {%0,%1,%2,%3};"
        : "+f"(c[0]), "+f"(c[1]), "+f"(c[2]), "+f"(c[3])
        : "r"(a[0]), "r"(a[1]), "r"(a[2]), "r"(a[3]), "r"(b0), "r"(b1));
}

__global__ void __launch_bounds__(256, 2) swa_mma(
    const float* __restrict__ Q,
    const float* __restrict__ K,
    const float* __restrict__ V,
    float* __restrict__ O)
{
    extern __shared__ char smem[];
    const unsigned sb = s2u(smem);

    const int h    = blockIdx.y;
    const int q0   = blockIdx.x * TQ;
    const int tid  = threadIdx.x;
    const int lane = tid & 31;
    const int w    = tid >> 5;
    const int wq   = w & 3;             // query group of 16
    const int sp   = w >> 2;            // key split 0/1
    const int base = q0 - WIN;          // global key of smem row 0

    // ---- hoist Q gmem loads (overlap DRAM latency with staging below) ----
    const int qw   = q0 + 16 * wq;
    const int r    = lane >> 2;
    const int col0 = (lane & 3) * 2;
    float2 e[4][4];
    {
        const float* Q0 = Q + (size_t)((qw + r)     * NH + h) * HD;
        const float* Q8 = Q + (size_t)((qw + r + 8) * NH + h) * HD;
        #pragma unroll
        for (int kt = 0; kt < 4; kt++) {
            e[kt][0] = *reinterpret_cast<const float2*>(Q0 + kt*16 + col0);
            e[kt][1] = *reinterpret_cast<const float2*>(Q8 + kt*16 + col0);
            e[kt][2] = *reinterpret_cast<const float2*>(Q0 + kt*16 + col0 + 8);
            e[kt][3] = *reinterpret_cast<const float2*>(Q8 + kt*16 + col0 + 8);
        }
    }

    // ---- stage K,V as single fp16 into swizzled smem ----
    #pragma unroll 2
    for (int idx = tid; idx < NROWS * 16; idx += 256) {
        const int row = idx >> 4;
        const int c   = idx & 15;
        const int k   = base + row;
        float4 kf = make_float4(0.f,0.f,0.f,0.f);
        float4 vf = make_float4(0.f,0.f,0.f,0.f);
        if ((unsigned)k < S_LEN) {
            const int off = (k * NH + h) * 16 + c;
            kf = reinterpret_cast<const float4*>(K)[off];
            vf = reinterpret_cast<const float4*>(V)[off];
        }
        const unsigned so = row * ROWB + ((((c >> 1) ^ (row & 7)) << 4)) + ((c & 1) << 3);
        *reinterpret_cast<uint2*>(smem + so) =
            make_uint2(pk16(kf.x, kf.y), pk16(kf.z, kf.w));
        *reinterpret_cast<uint2*>(smem + ARR + so) =
            make_uint2(pk16(vf.x, vf.y), pk16(vf.z, vf.w));
    }

    // ---- build Q fragments (scaled by 0.125*log2(e)), fp16 hi+lo ----
    const float sc = 0.125f * 1.44269504088896340736f;
    unsigned qh[4][4], ql[4][4];
    #pragma unroll
    for (int kt = 0; kt < 4; kt++) {
        #pragma unroll
        for (int j = 0; j < 4; j++) {
            float x = e[kt][j].x * sc, y = e[kt][j].y * sc;
            qh[kt][j] = pk16(x, y);
            float2 b = up16(qh[kt][j]);
            ql[kt][j] = pk16(x - b.x, y - b.y);
        }
    }

    __syncthreads();

    // ---- main loop: this split's key-steps of 16 keys ----
    float o[8][4];
    #pragma unroll
    for (int n = 0; n < 8; n++)
        #pragma unroll
        for (int j = 0; j < 4; j++) o[n][j] = 0.f;
    float lr = 0.f, lr8 = 0.f;

    const int gq   = lane >> 3;        // ldmatrix address group
    const int iq   = lane & 7;
    const int wrow = 16 * wq;
    const int rA0  = wrow + ((gq >> 1) << 3) + iq;   // QK addr row (pre ks)
    const int rB0  = wrow + ((gq & 1) << 3) + iq;    // PV addr row (pre ks)
    const int kbw  = base + wrow;                    // global key of warp row 0

    const int ksb = sp ? 5 : 0;
    const int kse = sp ? 9 : 5;

    #pragma unroll 1
    for (int ks = ksb; ks < kse; ks++) {
        // ---- QK: two n-tiles, 4 independent chains (qh,ql) x (n0,n1) ----
        float c0[4] = {0,0,0,0}, c1[4] = {0,0,0,0};
        float d0[4] = {0,0,0,0}, d1[4] = {0,0,0,0};
        const int rowA = rA0 + ks * 16;
        const unsigned aAbase = sb + rowA * ROWB;
        #pragma unroll
        for (int kt = 0; kt < 4; kt++) {
            const unsigned aK = aAbase + ((((2*kt) + (gq & 1)) ^ (rowA & 7)) << 4);
            unsigned b0,b1,b2,b3;
            ldsm4(b0,b1,b2,b3, aK);          // K fp16
            mma16816(c0, qh[kt], b0, b1);    // qh*K, n-tile 0
            mma16816(c1, qh[kt], b2, b3);    // qh*K, n-tile 1
            mma16816(d0, ql[kt], b0, b1);    // ql*K, n-tile 0
            mma16816(d1, ql[kt], b2, b3);    // ql*K, n-tile 1
        }
        #pragma unroll
        for (int j = 0; j < 4; j++) { c0[j] += d0[j]; c1[j] += d1[j]; }

        // ---- mask + exp2 (scores already in log2 domain) ----
        const int nta  = 2 * ks;
        const int d00  = nta*8 + col0 - 64 - r;   // key - query for c=0,h=0
        const int keyb = kbw + nta*8 + col0;
        #pragma unroll
        for (int t2 = 0; t2 < 2; t2++) {
            float* cc = t2 ? c1 : c0;
            const int dd = d00 + 8*t2;
            const int kk = keyb + 8*t2;
            float p0 = ((unsigned)(dd + 64)     <= 128 && (unsigned)kk     < S_LEN) ? ex2(cc[0]) : 0.f;
            float p1 = ((unsigned)(dd + 65)     <= 128 && (unsigned)(kk+1) < S_LEN) ? ex2(cc[1]) : 0.f;
            float p2 = ((unsigned)(dd + 56)     <= 128 && (unsigned)kk     < S_LEN) ? ex2(cc[2]) : 0.f;
            float p3 = ((unsigned)(dd + 57)     <= 128 && (unsigned)(kk+1) < S_LEN) ? ex2(cc[3]) : 0.f;
            cc[0]=p0; cc[1]=p1; cc[2]=p2; cc[3]=p3;
            lr  += p0 + p1;
            lr8 += p2 + p3;
        }

        // ---- P fragment (accum layout == A layout), single fp16 ----
        unsigned ph[4];
        ph[0] = pk16(c0[0], c0[1]); ph[1] = pk16(c0[2], c0[3]);
        ph[2] = pk16(c1[0], c1[1]); ph[3] = pk16(c1[2], c1[3]);

        // ---- PV: 8 n-tiles of dims, single term ----
        const int rowB = rB0 + ks * 16;
        const unsigned aBbase = sb + ARR + rowB * ROWB;
        #pragma unroll
        for (int dq = 0; dq < 4; dq++) {
            const unsigned aV = aBbase + ((((2*dq) + (gq >> 1)) ^ (rowB & 7)) << 4);
            unsigned v0,v1,v2,v3;
            ldsm4t(v0,v1,v2,v3, aV);         // V fp16
            mma16816(o[2*dq],   ph, v0, v1);
            mma16816(o[2*dq+1], ph, v2, v3);
        }
    }

    // ---- combine the two key splits through reused smem tile ----
    __syncthreads();                 // all tile reads done; smem is scratch now

    float* scr  = reinterpret_cast<float*>(smem);      // [4][32][36] floats
    float* scrL = scr + 4*32*36;                        // [4][32][2]

    if (sp == 1) {
        float4* ap = reinterpret_cast<float4*>(scr + (wq*32 + lane) * 36);
        #pragma unroll
        for (int n = 0; n < 8; n++)
            ap[n] = make_float4(o[n][0], o[n][1], o[n][2], o[n][3]);
        scrL[(wq*32 + lane)*2 + 0] = lr;
        scrL[(wq*32 + lane)*2 + 1] = lr8;
    }
    __syncthreads();

    if (sp == 0) {
        const float4* ap = reinterpret_cast<const float4*>(scr + (wq*32 + lane) * 36);
        #pragma unroll
        for (int n = 0; n < 8; n++) {
            const float4 b = ap[n];
            o[n][0] += b.x; o[n][1] += b.y; o[n][2] += b.z; o[n][3] += b.w;
        }
        lr  += scrL[(wq*32 + lane)*2 + 0];
        lr8 += scrL[(wq*32 + lane)*2 + 1];

        lr  += __shfl_xor_sync(0xffffffffu, lr, 1);
        lr  += __shfl_xor_sync(0xffffffffu, lr, 2);
        lr8 += __shfl_xor_sync(0xffffffffu, lr8, 1);
        lr8 += __shfl_xor_sync(0xffffffffu, lr8, 2);
        const float inv  = 1.0f / lr;
        const float inv8 = 1.0f / lr8;

        float* O0 = O + (size_t)((qw + r)     * NH + h) * HD;
        float* O8 = O + (size_t)((qw + r + 8) * NH + h) * HD;
        #pragma unroll
        for (int n = 0; n < 8; n++) {
            *reinterpret_cast<float2*>(O0 + n*8 + col0) =
                make_float2(o[n][0] * inv,  o[n][1] * inv);
            *reinterpret_cast<float2*>(O8 + n*8 + col0) =
                make_float2(o[n][2] * inv8, o[n][3] * inv8);
        }
    }
}

extern "C" void kernel_launch(void* const* d_in, const int* in_sizes, int n_in,
                              void* d_out, int out_size)
{
    const float* Q = (const float*)d_in[0];
    const float* K = (const float*)d_in[1];
    const float* V = (const float*)d_in[2];
    float* O = (float*)d_out;

    cudaFuncSetAttribute(swa_mma, cudaFuncAttributeMaxDynamicSharedMemorySize,
                         SMEM_BYTES);

    dim3 grid(S_LEN / TQ, NH);
    swa_mma<<<grid, 256, SMEM_BYTES>>>(Q, K, V, O);
}

// round 16
// speedup vs baseline: 1.4119x; 1.4030x over previous
#include <cuda_runtime.h>
#include <cuda_fp16.h>

// Sliding-window attention B=1,S=2048,H=8,D=64,win +-64, fp32 in/out.
// R16: fp16 MMA path (2-term QK, 1-term PV) +
//  - seq-bound masks removed: OOB rows zero-filled => score==0 exactly =>
//    p==1 exactly, V contribution 0; denominator corrected by integer
//    n_oob(q) in the epilogue (exact).
//  - window mask only on edge key-steps (0 and 8); steps 1..7 unmasked.
//  - fully unrolled, templated key-steps for cross-step pipelining.
// 8 warps/block: warp (wq,sp): queries q0+16wq..+15, steps sp=0:0..4,
// sp=1:5..8; split partials combined through reused smem.

#define S_LEN  2048
#define NH     8
#define HD     64
#define WIN    64
#define TQ     64
#define NROWS  192
#define ROWB   128                  // bytes per fp16 row (64*2)
#define ARR    (NROWS*ROWB)         // 24576 B per array
#define SMEM_BYTES (2*ARR)          // Kh, Vh = 49152 B

__device__ __forceinline__ unsigned pk16(float lo, float hi) {
    unsigned d;
    asm("cvt.rn.f16x2.f32 %0, %1, %2;" : "=r"(d) : "f"(hi), "f"(lo));
    return d;
}
__device__ __forceinline__ float2 up16(unsigned v) {
    __half2 h = *reinterpret_cast<__half2*>(&v);
    return __half22float2(h);
}
__device__ __forceinline__ float ex2(float x) {
    float y; asm("ex2.approx.f32 %0, %1;" : "=f"(y) : "f"(x)); return y;
}
__device__ __forceinline__ unsigned s2u(const void* p) {
    unsigned a;
    asm("{ .reg .u64 t; cvta.to.shared.u64 t, %1; cvt.u32.u64 %0, t; }"
        : "=r"(a) : "l"(p));
    return a;
}
__device__ __forceinline__ void ldsm4(unsigned& r0, unsigned& r1, unsigned& r2,
                                      unsigned& r3, unsigned a) {
    asm volatile("ldmatrix.sync.aligned.m8n8.x4.shared.b16 {%0,%1,%2,%3}, [%4];"
                 : "=r"(r0), "=r"(r1), "=r"(r2), "=r"(r3) : "r"(a));
}
__device__ __forceinline__ void ldsm4t(unsigned& r0, unsigned& r1, unsigned& r2,
                                       unsigned& r3, unsigned a) {
    asm volatile("ldmatrix.sync.aligned.m8n8.x4.trans.shared.b16 {%0,%1,%2,%3}, [%4];"
                 : "=r"(r0), "=r"(r1), "=r"(r2), "=r"(r3) : "r"(a));
}
__device__ __forceinline__ void mma16816(float c[4], const unsigned a[4],
                                         unsigned b0, unsigned b1) {
    asm volatile(
        "mma.sync.aligned.m16n8k16.row.col.f32.f16.f16.f32 "
        "{%0,%1,%2,%3}, {%4,%5,%6,%7}, {%8,%9}, {%0,%1,%2,%3};"
        : "+f"(c[0]), "+f"(c[1]), "+f"(c[2]), "+f"(c[3])
        : "r"(a[0]), "r"(a[1]), "r"(a[2]), "r"(a[3]), "r"(b0), "r"(b1));
}

// One 16-key step. MLO: mask dist<-64 (step 0). MHI: mask dist>64 (step 8).
template<int KS, bool MLO, bool MHI>
__device__ __forceinline__ void swa_step(
    unsigned sb, int rA0, int rB0, int gq, int col0r,
    const unsigned qh[4][4], const unsigned ql[4][4],
    float o[8][4], float& lr, float& lr8)
{
    float c0[4]={0,0,0,0}, c1[4]={0,0,0,0};
    float d0[4]={0,0,0,0}, d1[4]={0,0,0,0};
    const int rowA = rA0 + KS*16;
    const unsigned aAbase = sb + rowA*ROWB;
    #pragma unroll
    for (int kt = 0; kt < 4; kt++) {
        const unsigned aK = aAbase + ((((2*kt) + (gq & 1)) ^ (rowA & 7)) << 4);
        unsigned b0,b1,b2,b3;
        ldsm4(b0,b1,b2,b3, aK);
        mma16816(c0, qh[kt], b0, b1);
        mma16816(c1, qh[kt], b2, b3);
        mma16816(d0, ql[kt], b0, b1);
        mma16816(d1, ql[kt], b2, b3);
    }
    #pragma unroll
    for (int j = 0; j < 4; j++) { c0[j] += d0[j]; c1[j] += d1[j]; }

    // exp2 (+ window mask on edge steps only)
    const int d00 = KS*16 + col0r;          // dist for p0 of n-tile 0
    #pragma unroll
    for (int t2 = 0; t2 < 2; t2++) {
        float* cc = t2 ? c1 : c0;
        const int dd = d00 + 8*t2;
        float p0 = ex2(cc[0]);
        float p1 = ex2(cc[1]);
        float p2 = ex2(cc[2]);
        float p3 = ex2(cc[3]);
        if (MLO) {
            p0 = (dd     >= -64) ? p0 : 0.f;
            p1 = (dd + 1 >= -64) ? p1 : 0.f;
            p2 = (dd - 8 >= -64) ? p2 : 0.f;
            p3 = (dd - 7 >= -64) ? p3 : 0.f;
        }
        if (MHI) {
            p0 = (dd     <= 64) ? p0 : 0.f;
            p1 = (dd + 1 <= 64) ? p1 : 0.f;
            p2 = (dd - 8 <= 64) ? p2 : 0.f;
            p3 = (dd - 7 <= 64) ? p3 : 0.f;
        }
        cc[0]=p0; cc[1]=p1; cc[2]=p2; cc[3]=p3;
        lr  += p0 + p1;
        lr8 += p2 + p3;
    }

    // P fragment (accum layout == A layout), single fp16
    unsigned ph[4];
    ph[0] = pk16(c0[0], c0[1]); ph[1] = pk16(c0[2], c0[3]);
    ph[2] = pk16(c1[0], c1[1]); ph[3] = pk16(c1[2], c1[3]);

    // PV
    const int rowB = rB0 + KS*16;
    const unsigned aBbase = sb + ARR + rowB*ROWB;
    #pragma unroll
    for (int dq = 0; dq < 4; dq++) {
        const unsigned aV = aBbase + ((((2*dq) + (gq >> 1)) ^ (rowB & 7)) << 4);
        unsigned v0,v1,v2,v3;
        ldsm4t(v0,v1,v2,v3, aV);
        mma16816(o[2*dq],   ph, v0, v1);
        mma16816(o[2*dq+1], ph, v2, v3);
    }
}

__global__ void __launch_bounds__(256, 2) swa_mma(
    const float* __restrict__ Q,
    const float* __restrict__ K,
    const float* __restrict__ V,
    float* __restrict__ O)
{
    extern __shared__ char smem[];
    const unsigned sb = s2u(smem);

    const int h    = blockIdx.y;
    const int q0   = blockIdx.x * TQ;
    const int tid  = threadIdx.x;
    const int lane = tid & 31;
    const int w    = tid >> 5;
    const int wq   = w & 3;             // query group of 16
    const int sp   = w >> 2;            // key split 0/1
    const int base = q0 - WIN;          // global key of smem row 0

    // ---- hoist Q gmem loads (overlap DRAM latency with staging below) ----
    const int qw   = q0 + 16 * wq;
    const int r    = lane >> 2;
    const int col0 = (lane & 3) * 2;
    float2 e[4][4];
    {
        const float* Q0 = Q + (size_t)((qw + r)     * NH + h) * HD;
        const float* Q8 = Q + (size_t)((qw + r + 8) * NH + h) * HD;
        #pragma unroll
        for (int kt = 0; kt < 4; kt++) {
            e[kt][0] = *reinterpret_cast<const float2*>(Q0 + kt*16 + col0);
            e[kt][1] = *reinterpret_cast<const float2*>(Q8 + kt*16 + col0);
            e[kt][2] = *reinterpret_cast<const float2*>(Q0 + kt*16 + col0 + 8);
            e[kt][3] = *reinterpret_cast<const float2*>(Q8 + kt*16 + col0 + 8);
        }
    }

    // ---- stage K,V as fp16 into swizzled smem (zero-fill OOB rows) ----
    #pragma unroll 2
    for (int idx = tid; idx < NROWS * 16; idx += 256) {
        const int row = idx >> 4;
        const int c   = idx & 15;
        const int k   = base + row;
        float4 kf = make_float4(0.f,0.f,0.f,0.f);
        float4 vf = make_float4(0.f,0.f,0.f,0.f);
        if ((unsigned)k < S_LEN) {
            const int off = (k * NH + h) * 16 + c;
            kf = reinterpret_cast<const float4*>(K)[off];
            vf = reinterpret_cast<const float4*>(V)[off];
        }
        const unsigned so = row * ROWB + ((((c >> 1) ^ (row & 7)) << 4)) + ((c & 1) << 3);
        *reinterpret_cast<uint2*>(smem + so) =
            make_uint2(pk16(kf.x, kf.y), pk16(kf.z, kf.w));
        *reinterpret_cast<uint2*>(smem + ARR + so) =
            make_uint2(pk16(vf.x, vf.y), pk16(vf.z, vf.w));
    }

    // ---- build Q fragments (scaled by 0.125*log2(e)), fp16 hi+lo ----
    const float sc = 0.125f * 1.44269504088896340736f;
    unsigned qh[4][4], ql[4][4];
    #pragma unroll
    for (int kt = 0; kt < 4; kt++) {
        #pragma unroll
        for (int j = 0; j < 4; j++) {
            float x = e[kt][j].x * sc, y = e[kt][j].y * sc;
            qh[kt][j] = pk16(x, y);
            float2 b = up16(qh[kt][j]);
            ql[kt][j] = pk16(x - b.x, y - b.y);
        }
    }

    __syncthreads();

    // ---- main loop: this split's key-steps, fully unrolled ----
    float o[8][4];
    #pragma unroll
    for (int n = 0; n < 8; n++)
        #pragma unroll
        for (int j = 0; j < 4; j++) o[n][j] = 0.f;
    float lr = 0.f, lr8 = 0.f;

    const int gq    = lane >> 3;
    const int iq    = lane & 7;
    const int wrow  = 16 * wq;
    const int rA0   = wrow + ((gq >> 1) << 3) + iq;
    const int rB0   = wrow + ((gq & 1) << 3) + iq;
    const int col0r = col0 - 64 - r;        // dist of p0 at KS=0

    if (sp == 0) {
        swa_step<0, true,  false>(sb, rA0, rB0, gq, col0r, qh, ql, o, lr, lr8);
        swa_step<1, false, false>(sb, rA0, rB0, gq, col0r, qh, ql, o, lr, lr8);
        swa_step<2, false, false>(sb, rA0, rB0, gq, col0r, qh, ql, o, lr, lr8);
        swa_step<3, false, false>(sb, rA0, rB0, gq, col0r, qh, ql, o, lr, lr8);
        swa_step<4, false, false>(sb, rA0, rB0, gq, col0r, qh, ql, o, lr, lr8);
    } else {
        swa_step<5, false, false>(sb, rA0, rB0, gq, col0r, qh, ql, o, lr, lr8);
        swa_step<6, false, false>(sb, rA0, rB0, gq, col0r, qh, ql, o, lr, lr8);
        swa_step<7, false, false>(sb, rA0, rB0, gq, col0r, qh, ql, o, lr, lr8);
        swa_step<8, false, true >(sb, rA0, rB0, gq, col0r, qh, ql, o, lr, lr8);
    }

    // ---- combine the two key splits through reused smem tile ----
    __syncthreads();                 // all tile reads done; smem is scratch now

    float* scr  = reinterpret_cast<float*>(smem);      // [4][32][36] floats
    float* scrL = scr + 4*32*36;                        // [4][32][2]

    if (sp == 1) {
        float4* ap = reinterpret_cast<float4*>(scr + (wq*32 + lane) * 36);
        #pragma unroll
        for (int n = 0; n < 8; n++)
            ap[n] = make_float4(o[n][0], o[n][1], o[n][2], o[n][3]);
        scrL[(wq*32 + lane)*2 + 0] = lr;
        scrL[(wq*32 + lane)*2 + 1] = lr8;
    }
    __syncthreads();

    if (sp == 0) {
        const float4* ap = reinterpret_cast<const float4*>(scr + (wq*32 + lane) * 36);
        #pragma unroll
        for (int n = 0; n < 8; n++) {
            const float4 b = ap[n];
            o[n][0] += b.x; o[n][1] += b.y; o[n][2] += b.z; o[n][3] += b.w;
        }
        lr  += scrL[(wq*32 + lane)*2 + 0];
        lr8 += scrL[(wq*32 + lane)*2 + 1];

        lr  += __shfl_xor_sync(0xffffffffu, lr, 1);
        lr  += __shfl_xor_sync(0xffffffffu, lr, 2);
        lr8 += __shfl_xor_sync(0xffffffffu, lr8, 1);
        lr8 += __shfl_xor_sync(0xffffffffu, lr8, 2);

        // exact OOB correction: each OOB window key contributed exactly 1.0
        const int q  = qw + r;
        const int oA = max(0, WIN - q)       + max(0, q       - (S_LEN-1-WIN));
        const int oB = max(0, WIN - (q + 8)) + max(0, (q + 8) - (S_LEN-1-WIN));
        const float inv  = 1.0f / (lr  - (float)oA);
        const float inv8 = 1.0f / (lr8 - (float)oB);

        float* O0 = O + (size_t)((qw + r)     * NH + h) * HD;
        float* O8 = O + (size_t)((qw + r + 8) * NH + h) * HD;
        #pragma unroll
        for (int n = 0; n < 8; n++) {
            *reinterpret_cast<float2*>(O0 + n*8 + col0) =
                make_float2(o[n][0] * inv,  o[n][1] * inv);
            *reinterpret_cast<float2*>(O8 + n*8 + col0) =
                make_float2(o[n][2] * inv8, o[n][3] * inv8);
        }
    }
}

extern "C" void kernel_launch(void* const* d_in, const int* in_sizes, int n_in,
                              void* d_out, int out_size)
{
    const float* Q = (const float*)d_in[0];
    const float* K = (const float*)d_in[1];
    const float* V = (const float*)d_in[2];
    float* O = (float*)d_out;

    cudaFuncSetAttribute(swa_mma, cudaFuncAttributeMaxDynamicSharedMemorySize,
                         SMEM_BYTES);

    dim3 grid(S_LEN / TQ, NH);
    swa_mma<<<grid, 256, SMEM_BYTES>>>(Q, K, V, O);
}